// round 1
// baseline (speedup 1.0000x reference)
#include <cuda_runtime.h>
#include <cstdint>

#define B_ 64
#define N_ 197
#define C_ 768
#define H_ 12
#define DH_ 64
#define M_ (B_*N_)          // 12608
#define NN_ (N_*N_)         // 38809
#define THREEC_ 2304
#define NUM_REL_ 732
#define QSCALE 0.125f       // 64^-0.5
#define KTP 224             // padded k-columns in smem (>=197, no guard in hot loop)

// ---------------- scratch (static device globals; allocation-free) ----------------
__device__ float g_q[(size_t)B_*H_*N_*DH_];
__device__ float g_k[(size_t)B_*H_*N_*DH_];
__device__ float g_v[(size_t)B_*H_*N_*DH_];
__device__ float g_attn [(size_t)B_*H_*NN_];
__device__ float g_attn2[(size_t)B_*H_*NN_];
__device__ float g_ctx[(size_t)M_*C_];

// =====================================================================
// Kernel 1: qkv = (x @ W^T + bias) * ssf_scale + ssf_shift, scatter to
// q/k/v in [B,H,N,DH]; q additionally scaled by QSCALE.
// Tile: BM=64, BN=128, BK=16, 256 threads, 4x8 per thread.
// grid = (197, 18)
// =====================================================================
__global__ __launch_bounds__(256) void qkv_gemm(
    const float* __restrict__ x, const float* __restrict__ w,
    const float* __restrict__ qb, const float* __restrict__ vb,
    const float* __restrict__ sscale, const float* __restrict__ sshift)
{
    __shared__ __align__(16) float As[16][68];
    __shared__ __align__(16) float Bs[16][136];
    const int tid  = threadIdx.x;
    const int row0 = blockIdx.x * 64;
    const int col0 = blockIdx.y * 128;
    const int tx = tid & 15, ty = tid >> 4;
    const int lr = tid >> 2;            // 0..63
    const int lk = (tid & 3) << 2;      // 0,4,8,12

    float acc[4][8];
#pragma unroll
    for (int i = 0; i < 4; i++)
#pragma unroll
        for (int j = 0; j < 8; j++) acc[i][j] = 0.f;

    const float* xA  = x + (size_t)(row0 + lr) * C_ + lk;
    const float* wB0 = w + (size_t)(col0 + lr) * C_ + lk;
    const float* wB1 = wB0 + (size_t)64 * C_;

    for (int k0 = 0; k0 < C_; k0 += 16) {
        float4 a  = *(const float4*)(xA  + k0);
        float4 b0 = *(const float4*)(wB0 + k0);
        float4 b1 = *(const float4*)(wB1 + k0);
        As[lk+0][lr] = a.x;  As[lk+1][lr] = a.y;  As[lk+2][lr] = a.z;  As[lk+3][lr] = a.w;
        Bs[lk+0][lr] = b0.x; Bs[lk+1][lr] = b0.y; Bs[lk+2][lr] = b0.z; Bs[lk+3][lr] = b0.w;
        Bs[lk+0][lr+64] = b1.x; Bs[lk+1][lr+64] = b1.y; Bs[lk+2][lr+64] = b1.z; Bs[lk+3][lr+64] = b1.w;
        __syncthreads();
#pragma unroll
        for (int kk = 0; kk < 16; kk++) {
            float4 av  = *(const float4*)&As[kk][ty << 2];
            float4 bv0 = *(const float4*)&Bs[kk][tx << 3];
            float4 bv1 = *(const float4*)&Bs[kk][(tx << 3) + 4];
            float aa[4] = {av.x, av.y, av.z, av.w};
            float bb[8] = {bv0.x, bv0.y, bv0.z, bv0.w, bv1.x, bv1.y, bv1.z, bv1.w};
#pragma unroll
            for (int i = 0; i < 4; i++)
#pragma unroll
                for (int j = 0; j < 8; j++)
                    acc[i][j] = fmaf(aa[i], bb[j], acc[i][j]);
        }
        __syncthreads();
    }

    const int m_base = row0 + (ty << 2);
    const int n_base = col0 + (tx << 3);
    const int which = n_base / C_;            // uniform per block (768 % 128 == 0)
    const int rem_base = n_base - which * C_;
#pragma unroll
    for (int i = 0; i < 4; i++) {
        int m = m_base + i;
        int b = m / N_, t = m - b * N_;
#pragma unroll
        for (int j = 0; j < 8; j++) {
            int rem = rem_base + j;
            int h = rem >> 6, d = rem & 63;
            int n = which * C_ + rem;
            float bias = (which == 0) ? qb[rem] : ((which == 2) ? vb[rem] : 0.f);
            float val = (acc[i][j] + bias) * sscale[n] + sshift[n];
            size_t off = (((size_t)(b * H_ + h)) * N_ + t) * DH_ + d;
            if (which == 0)      g_q[off] = val * QSCALE;
            else if (which == 1) g_k[off] = val;
            else                 g_v[off] = val;
        }
    }
}

// =====================================================================
// Kernel 2: attn[b,h] = softmax(q @ k^T + rel_bias_gather)
// one block per (b,h); kT + q staged in smem; warp handles 4 rows.
// dynamic smem = (64*KTP + 197*64 + 732) * 4 bytes
// =====================================================================
__global__ __launch_bounds__(256) void scores_kernel(
    const float* __restrict__ rel_table, const int* __restrict__ rel_index)
{
    extern __shared__ float sm[];
    float* kT  = sm;                 // [64][KTP]
    float* qs  = kT + 64 * KTP;      // [197][64]
    float* tbl = qs + N_ * DH_;      // [732]

    const int tid = threadIdx.x;
    const int bh = blockIdx.x;
    const int h = bh % H_;
    const float* kp = g_k + (size_t)bh * N_ * DH_;
    const float* qp = g_q + (size_t)bh * N_ * DH_;

    for (int idx = tid; idx < N_ * DH_; idx += 256) {
        int m = idx >> 6, d = idx & 63;
        kT[d * KTP + m] = kp[idx];
        qs[idx] = qp[idx];
    }
    for (int idx = tid; idx < 64 * (KTP - N_); idx += 256) {
        int d = idx / (KTP - N_), m = N_ + idx % (KTP - N_);
        kT[d * KTP + m] = 0.f;
    }
    for (int idx = tid; idx < NUM_REL_; idx += 256)
        tbl[idx] = rel_table[idx * H_ + h];
    __syncthreads();

    const int w = tid >> 5, l = tid & 31;
    float* outp = g_attn + (size_t)bh * NN_;

    for (int n0 = w * 4; n0 < N_; n0 += 32) {
        int nr[4];
#pragma unroll
        for (int r = 0; r < 4; r++) nr[r] = min(n0 + r, N_ - 1);
        float acc[4][7];
#pragma unroll
        for (int r = 0; r < 4; r++)
#pragma unroll
            for (int j = 0; j < 7; j++) acc[r][j] = 0.f;

#pragma unroll 4
        for (int d = 0; d < DH_; d++) {
            float qv[4];
#pragma unroll
            for (int r = 0; r < 4; r++) qv[r] = qs[nr[r] * 64 + d];
#pragma unroll
            for (int j = 0; j < 7; j++) {
                float kv = kT[d * KTP + l + 32 * j];
#pragma unroll
                for (int r = 0; r < 4; r++) acc[r][j] = fmaf(qv[r], kv, acc[r][j]);
            }
        }

#pragma unroll
        for (int r = 0; r < 4; r++) {
            int n = n0 + r;
            if (n >= N_) break;
            const int* ridx = rel_index + n * N_;
            float s[7];
#pragma unroll
            for (int j = 0; j < 7; j++) {
                int m = l + 32 * j;
                s[j] = (m < N_) ? acc[r][j] + tbl[ridx[m]] : -1e30f;
            }
            float mx = s[0];
#pragma unroll
            for (int j = 1; j < 7; j++) mx = fmaxf(mx, s[j]);
#pragma unroll
            for (int o = 16; o; o >>= 1) mx = fmaxf(mx, __shfl_xor_sync(0xffffffffu, mx, o));
            float sum = 0.f;
#pragma unroll
            for (int j = 0; j < 7; j++) { float e = __expf(s[j] - mx); s[j] = e; sum += e; }
#pragma unroll
            for (int o = 16; o; o >>= 1) sum += __shfl_xor_sync(0xffffffffu, sum, o);
            float inv = 1.f / sum;
#pragma unroll
            for (int j = 0; j < 7; j++) {
                int m = l + 32 * j;
                if (m < N_) outp[(size_t)n * N_ + m] = s[j] * inv;
            }
        }
    }
}

// =====================================================================
// Kernel 3: attn2[b,k,:,:] = sum_h attn[b,h,:,:] * (coeff[k,h] + (h==k))
// grid = (ceil(NN/256), 64)
// =====================================================================
__global__ __launch_bounds__(256) void mix_kernel(const float* __restrict__ coeff)
{
    __shared__ float mixs[12][13];
    const int tid = threadIdx.x;
    if (tid < 144) {
        int k = tid / 12, h = tid % 12;
        mixs[h][k] = coeff[k * 12 + h] + ((h == k) ? 1.f : 0.f);
    }
    __syncthreads();

    const int b = blockIdx.y;
    const int idx = blockIdx.x * 256 + tid;
    if (idx >= NN_) return;
    const float* ap = g_attn + (size_t)b * H_ * NN_ + idx;
    float a[12];
#pragma unroll
    for (int h = 0; h < 12; h++) a[h] = ap[(size_t)h * NN_];
    float* op = g_attn2 + (size_t)b * H_ * NN_ + idx;
#pragma unroll
    for (int k = 0; k < 12; k++) {
        float s = 0.f;
#pragma unroll
        for (int h = 0; h < 12; h++) s = fmaf(a[h], mixs[h][k], s);
        op[(size_t)k * NN_] = s;
    }
}

// =====================================================================
// Kernel 4: ctx[b,n,h*64+d] = attn2[b,h] @ v[b,h]  (197x197x64 per bh)
// Tile: BM=64 (n), BN=64 (d), BK=16; grid = (4, 768)
// =====================================================================
__global__ __launch_bounds__(256) void av_gemm()
{
    __shared__ __align__(16) float As[16][68];
    __shared__ __align__(16) float Vs[16][68];
    const int tid = threadIdx.x;
    const int bh = blockIdx.y;
    const int row0 = blockIdx.x * 64;
    const float* A = g_attn2 + (size_t)bh * NN_;
    const float* V = g_v + (size_t)bh * N_ * DH_;
    const int tx = tid & 15, ty = tid >> 4;
    const int vr = tid >> 4;            // 0..15 (k row for V)
    const int vc = (tid & 15) << 2;     // d offset

    float acc[4][4];
#pragma unroll
    for (int i = 0; i < 4; i++)
#pragma unroll
        for (int j = 0; j < 4; j++) acc[i][j] = 0.f;

    for (int k0 = 0; k0 < N_; k0 += 16) {
#pragma unroll
        for (int u = 0; u < 4; u++) {
            int idx = tid + u * 256;
            int r = idx >> 4, kc = idx & 15;
            int n = row0 + r, k = k0 + kc;
            As[kc][r] = (n < N_ && k < N_) ? A[(size_t)n * N_ + k] : 0.f;
        }
        {
            int k = k0 + vr;
            float4 vv = (k < N_) ? *(const float4*)(V + (size_t)k * DH_ + vc)
                                 : make_float4(0.f, 0.f, 0.f, 0.f);
            *(float4*)&Vs[vr][vc] = vv;
        }
        __syncthreads();
#pragma unroll
        for (int kk = 0; kk < 16; kk++) {
            float4 av = *(const float4*)&As[kk][ty << 2];
            float4 bv = *(const float4*)&Vs[kk][tx << 2];
            float aa[4] = {av.x, av.y, av.z, av.w};
            float bb[4] = {bv.x, bv.y, bv.z, bv.w};
#pragma unroll
            for (int i = 0; i < 4; i++)
#pragma unroll
                for (int j = 0; j < 4; j++)
                    acc[i][j] = fmaf(aa[i], bb[j], acc[i][j]);
        }
        __syncthreads();
    }

    const int b = bh / H_, h = bh - b * H_;
#pragma unroll
    for (int i = 0; i < 4; i++) {
        int n = row0 + (ty << 2) + i;
        if (n < N_) {
            float* op = g_ctx + ((size_t)(b * N_ + n)) * C_ + h * DH_ + (tx << 2);
#pragma unroll
            for (int j = 0; j < 4; j++) op[j] = acc[i][j];
        }
    }
}

// =====================================================================
// Kernel 5: out = (ctx @ proj_w^T + proj_b) * ssf_scale + ssf_shift
// Tile: BM=64, BN=128, BK=16; grid = (197, 6)
// =====================================================================
__global__ __launch_bounds__(256) void proj_gemm(
    const float* __restrict__ w, const float* __restrict__ pb,
    const float* __restrict__ sscale, const float* __restrict__ sshift,
    float* __restrict__ out)
{
    __shared__ __align__(16) float As[16][68];
    __shared__ __align__(16) float Bs[16][136];
    const int tid  = threadIdx.x;
    const int row0 = blockIdx.x * 64;
    const int col0 = blockIdx.y * 128;
    const int tx = tid & 15, ty = tid >> 4;
    const int lr = tid >> 2;
    const int lk = (tid & 3) << 2;

    float acc[4][8];
#pragma unroll
    for (int i = 0; i < 4; i++)
#pragma unroll
        for (int j = 0; j < 8; j++) acc[i][j] = 0.f;

    const float* xA  = g_ctx + (size_t)(row0 + lr) * C_ + lk;
    const float* wB0 = w + (size_t)(col0 + lr) * C_ + lk;
    const float* wB1 = wB0 + (size_t)64 * C_;

    for (int k0 = 0; k0 < C_; k0 += 16) {
        float4 a  = *(const float4*)(xA  + k0);
        float4 b0 = *(const float4*)(wB0 + k0);
        float4 b1 = *(const float4*)(wB1 + k0);
        As[lk+0][lr] = a.x;  As[lk+1][lr] = a.y;  As[lk+2][lr] = a.z;  As[lk+3][lr] = a.w;
        Bs[lk+0][lr] = b0.x; Bs[lk+1][lr] = b0.y; Bs[lk+2][lr] = b0.z; Bs[lk+3][lr] = b0.w;
        Bs[lk+0][lr+64] = b1.x; Bs[lk+1][lr+64] = b1.y; Bs[lk+2][lr+64] = b1.z; Bs[lk+3][lr+64] = b1.w;
        __syncthreads();
#pragma unroll
        for (int kk = 0; kk < 16; kk++) {
            float4 av  = *(const float4*)&As[kk][ty << 2];
            float4 bv0 = *(const float4*)&Bs[kk][tx << 3];
            float4 bv1 = *(const float4*)&Bs[kk][(tx << 3) + 4];
            float aa[4] = {av.x, av.y, av.z, av.w};
            float bb[8] = {bv0.x, bv0.y, bv0.z, bv0.w, bv1.x, bv1.y, bv1.z, bv1.w};
#pragma unroll
            for (int i = 0; i < 4; i++)
#pragma unroll
                for (int j = 0; j < 8; j++)
                    acc[i][j] = fmaf(aa[i], bb[j], acc[i][j]);
        }
        __syncthreads();
    }

    const int m_base = row0 + (ty << 2);
    const int n_base = col0 + (tx << 3);
#pragma unroll
    for (int i = 0; i < 4; i++) {
        int m = m_base + i;
#pragma unroll
        for (int j = 0; j < 8; j++) {
            int n = n_base + j;
            out[(size_t)m * C_ + n] = (acc[i][j] + pb[n]) * sscale[n] + sshift[n];
        }
    }
}

// =====================================================================
// Host launcher
// =====================================================================
extern "C" void kernel_launch(void* const* d_in, const int* in_sizes, int n_in,
                              void* d_out, int out_size)
{
    const float* x         = (const float*)d_in[0];
    const float* qkv_w     = (const float*)d_in[1];
    const float* q_bias    = (const float*)d_in[2];
    const float* v_bias    = (const float*)d_in[3];
    const float* ss_qkv    = (const float*)d_in[4];
    const float* sh_qkv    = (const float*)d_in[5];
    const float* rel_table = (const float*)d_in[6];
    const float* coeff     = (const float*)d_in[7];
    const float* proj_w    = (const float*)d_in[8];
    const float* proj_b    = (const float*)d_in[9];
    const float* ss_proj   = (const float*)d_in[10];
    const float* sh_proj   = (const float*)d_in[11];
    const int*   rel_index = (const int*)d_in[12];
    float* out = (float*)d_out;

    const int scores_smem = (64 * KTP + N_ * DH_ + NUM_REL_) * 4;   // 110704 B
    cudaFuncSetAttribute(scores_kernel, cudaFuncAttributeMaxDynamicSharedMemorySize, scores_smem);

    qkv_gemm<<<dim3(197, 18), 256>>>(x, qkv_w, q_bias, v_bias, ss_qkv, sh_qkv);
    scores_kernel<<<B_ * H_, 256, scores_smem>>>(rel_table, rel_index);
    mix_kernel<<<dim3((NN_ + 255) / 256, B_), 256>>>(coeff);
    av_gemm<<<dim3(4, B_ * H_), 256>>>();
    proj_gemm<<<dim3(197, 6), 256>>>(proj_w, proj_b, ss_proj, sh_proj, out);
}

// round 3
// speedup vs baseline: 2.3240x; 2.3240x over previous
#include <cuda_runtime.h>
#include <cuda_bf16.h>
#include <cstdint>

#define B_ 64
#define N_ 197
#define C_ 768
#define H_ 12
#define DH_ 64
#define M_ (B_*N_)          // 12608
#define NN_ (N_*N_)         // 38809
#define NUM_REL_ 732
#define QSCALE 0.125f
#define KTP 224
#define KP_ 2304            // packed K = 3*768
#define NCH_ 36             // K chunks of 64 bf16
#define SROW 72             // smem row stride in bf16 (64 + 8 pad)
#define SA_ (128*SROW*2)    // one smem tile: 18432 bytes

// ---------------- scratch ----------------
__device__ float g_q[(size_t)B_*H_*N_*DH_];
__device__ float g_k[(size_t)B_*H_*N_*DH_];
__device__ float g_v[(size_t)B_*H_*N_*DH_];
__device__ float g_attn [(size_t)B_*H_*NN_];
__device__ float g_attn2[(size_t)B_*H_*NN_];
__device__ float g_ctx[(size_t)M_*C_];
__device__ __nv_bfloat16 g_apack[(size_t)M_*KP_];     // packed activations [hi,hi,lo]
__device__ __nv_bfloat16 g_bqkv [(size_t)3*C_*KP_];   // packed qkv weights [hi,lo,hi]
__device__ __nv_bfloat16 g_bproj[(size_t)C_*KP_];     // packed proj weights

// ---------------- PTX helpers (baseline ISA only: sm_80-era) ----------------
__device__ __forceinline__ uint32_t smem_to_u32(const void* p) {
    uint32_t a;
    asm("{ .reg .u64 t; cvta.to.shared.u64 t, %1; cvt.u32.u64 %0, t; }" : "=r"(a) : "l"(p));
    return a;
}
#define CP_ASYNC16(sm, gp) \
    asm volatile("cp.async.cg.shared.global [%0], [%1], 16;" :: "r"(sm), "l"(gp))
#define CP_COMMIT()  asm volatile("cp.async.commit_group;" ::: "memory")
#define CP_WAIT0()   asm volatile("cp.async.wait_group 0;" ::: "memory")
#define LDSM_X4(r0,r1,r2,r3, addr) \
    asm volatile("ldmatrix.sync.aligned.m8n8.x4.shared.b16 {%0,%1,%2,%3}, [%4];" \
        : "=r"(r0), "=r"(r1), "=r"(r2), "=r"(r3) : "r"(addr))

__device__ __forceinline__ void mma16816(float* c, const uint32_t* a, uint32_t b0, uint32_t b1) {
    asm volatile("mma.sync.aligned.m16n8k16.row.col.f32.bf16.bf16.f32 "
        "{%0,%1,%2,%3}, {%4,%5,%6,%7}, {%8,%9}, {%0,%1,%2,%3};"
        : "+f"(c[0]), "+f"(c[1]), "+f"(c[2]), "+f"(c[3])
        : "r"(a[0]), "r"(a[1]), "r"(a[2]), "r"(a[3]), "r"(b0), "r"(b1));
}

// =====================================================================
// Pack kernels: f32 -> split bf16 along packed K
// A ordering: [hi, hi, lo];  B ordering: [hi, lo, hi]
// =====================================================================
__global__ __launch_bounds__(256) void pack_a(const float* __restrict__ src,
                                              __nv_bfloat16* __restrict__ dst, int total)
{
    int idx = blockIdx.x * 256 + threadIdx.x;
    if (idx >= total) return;
    int row = idx / C_, k = idx - row * C_;
    float v = src[idx];
    __nv_bfloat16 hi = __float2bfloat16(v);
    __nv_bfloat16 lo = __float2bfloat16(v - __bfloat162float(hi));
    size_t ro = (size_t)row * KP_;
    dst[ro + k] = hi; dst[ro + C_ + k] = hi; dst[ro + 2*C_ + k] = lo;
}
__global__ __launch_bounds__(256) void pack_b(const float* __restrict__ src,
                                              __nv_bfloat16* __restrict__ dst, int total)
{
    int idx = blockIdx.x * 256 + threadIdx.x;
    if (idx >= total) return;
    int row = idx / C_, k = idx - row * C_;
    float v = src[idx];
    __nv_bfloat16 hi = __float2bfloat16(v);
    __nv_bfloat16 lo = __float2bfloat16(v - __bfloat162float(hi));
    size_t ro = (size_t)row * KP_;
    dst[ro + k] = hi; dst[ro + C_ + k] = lo; dst[ro + 2*C_ + k] = hi;
}

// =====================================================================
// mma.sync GEMM: D[128,128] tile = A[128,KP] * B[128,KP]^T (K-major bf16)
// 256 threads = 8 warps (2 along M x 4 along N), warp tile 64x32.
// BK=64, cp.async double-buffered smem, ldmatrix fragments.
// MODE 0: qkv epilogue (bias+SSF, scatter to g_q/g_k/g_v)
// MODE 1: proj epilogue (bias+SSF -> out)
// =====================================================================
template<int MODE>
__global__ __launch_bounds__(256) void tc_gemm(
    const __nv_bfloat16* __restrict__ Ap, const __nv_bfloat16* __restrict__ Bp,
    const float* __restrict__ p_qb, const float* __restrict__ p_vb,
    const float* __restrict__ sscale, const float* __restrict__ sshift,
    float* __restrict__ outp)
{
    extern __shared__ char smem_raw[];
    const uint32_t sbase = smem_to_u32(smem_raw);
    // layout: Abuf0, Abuf1, Bbuf0, Bbuf1 (each SA_ bytes)
    const int tid = threadIdx.x;
    const int lane = tid & 31, wid = tid >> 5;
    const int wm = wid & 1;        // 0..1
    const int wn = wid >> 1;       // 0..3
    const int row0 = blockIdx.x * 128;
    const int col0 = blockIdx.y * 128;

    // ---- cp.async load indices: col fixed per thread, 4 rows ----
    const int lcol = tid & 7;           // uint4 index within row (8 per row)
    const int lrow = tid >> 3;          // 0..31; rows lrow + {0,32,64,96}
    const __nv_bfloat16* agp[4];
    const __nv_bfloat16* bgp[4];
#pragma unroll
    for (int u = 0; u < 4; u++) {
        int ar = min(row0 + lrow + u * 32, M_ - 1);
        agp[u] = Ap + (size_t)ar * KP_ + lcol * 8;
        bgp[u] = Bp + (size_t)(col0 + lrow + u * 32) * KP_ + lcol * 8;
    }
    const uint32_t ssto = (uint32_t)((lrow * SROW + lcol * 8) * 2);

    auto load_chunk = [&](int ch, int bsel) {
        const uint32_t abuf = sbase + bsel * SA_;
        const uint32_t bbuf = sbase + 2 * SA_ + bsel * SA_;
        const int ko = ch * 64;
#pragma unroll
        for (int u = 0; u < 4; u++) {
            CP_ASYNC16(abuf + ssto + u * 32 * SROW * 2, agp[u] + ko);
            CP_ASYNC16(bbuf + ssto + u * 32 * SROW * 2, bgp[u] + ko);
        }
        CP_COMMIT();
    };

    // ---- fragment addresses ----
    const uint32_t a_l = ((wm * 64 + (lane & 15)) * SROW + (lane >> 4) * 8) * 2;
    const uint32_t b_l = ((wn * 32 + (lane & 15)) * SROW + (lane >> 4) * 8) * 2;

    float acc[4][4][4];
#pragma unroll
    for (int i = 0; i < 4; i++)
#pragma unroll
        for (int j = 0; j < 4; j++)
#pragma unroll
            for (int r = 0; r < 4; r++) acc[i][j][r] = 0.f;

    load_chunk(0, 0);
    CP_WAIT0();
    __syncthreads();

    for (int ch = 0; ch < NCH_; ch++) {
        const int bsel = ch & 1;
        if (ch + 1 < NCH_) load_chunk(ch + 1, bsel ^ 1);

        const uint32_t abuf = sbase + bsel * SA_;
        const uint32_t bbuf = sbase + 2 * SA_ + bsel * SA_;
#pragma unroll
        for (int ks = 0; ks < 64; ks += 16) {
            uint32_t a[4][4];
#pragma unroll
            for (int mf = 0; mf < 4; mf++)
                LDSM_X4(a[mf][0], a[mf][1], a[mf][2], a[mf][3],
                        abuf + a_l + (mf * 16 * SROW + ks) * 2);
            uint32_t bq[2][4];
#pragma unroll
            for (int nf2 = 0; nf2 < 2; nf2++)
                LDSM_X4(bq[nf2][0], bq[nf2][1], bq[nf2][2], bq[nf2][3],
                        bbuf + b_l + (nf2 * 16 * SROW + ks) * 2);
#pragma unroll
            for (int mf = 0; mf < 4; mf++) {
#pragma unroll
                for (int nf = 0; nf < 4; nf++) {
                    const int h2 = nf >> 1, odd = nf & 1;
                    mma16816(acc[mf][nf], a[mf], bq[h2][odd], bq[h2][odd + 2]);
                }
            }
        }
        CP_WAIT0();
        __syncthreads();
    }

    // ---- epilogue ----
    const int rbase = row0 + wm * 64 + (lane >> 2);
    const int cbase = col0 + wn * 32 + (lane & 3) * 2;
#pragma unroll
    for (int mf = 0; mf < 4; mf++) {
#pragma unroll
        for (int half = 0; half < 2; half++) {
            const int m = rbase + mf * 16 + half * 8;
            if (m >= M_) continue;
            const int bi = m / N_, t = m - bi * N_;
#pragma unroll
            for (int nf = 0; nf < 4; nf++) {
                float v0 = acc[mf][nf][half * 2 + 0];
                float v1 = acc[mf][nf][half * 2 + 1];
                const int n0 = cbase + nf * 8;
                if (MODE == 0) {
                    const int which = col0 / C_;          // uniform per block
#pragma unroll
                    for (int j = 0; j < 2; j++) {
                        int nn = n0 + j;
                        int rem = nn - which * C_;
                        int h = rem >> 6, d = rem & 63;
                        float bias = (which == 0) ? p_qb[rem] : ((which == 2) ? p_vb[rem] : 0.f);
                        float val = ((j ? v1 : v0) + bias) * sscale[nn] + sshift[nn];
                        size_t off = (((size_t)(bi * H_ + h)) * N_ + t) * DH_ + d;
                        if (which == 0)      g_q[off] = val * QSCALE;
                        else if (which == 1) g_k[off] = val;
                        else                 g_v[off] = val;
                    }
                } else {
                    float* op = outp + (size_t)m * C_ + n0;
                    op[0] = (v0 + p_qb[n0])     * sscale[n0]     + sshift[n0];
                    op[1] = (v1 + p_qb[n0 + 1]) * sscale[n0 + 1] + sshift[n0 + 1];
                }
            }
        }
    }
}

// =====================================================================
// Kernel: attn[b,h] = softmax(q @ k^T + rel_bias)
// =====================================================================
__global__ __launch_bounds__(256) void scores_kernel(
    const float* __restrict__ rel_table, const int* __restrict__ rel_index)
{
    extern __shared__ float sm[];
    float* kT  = sm;
    float* qs  = kT + 64 * KTP;
    float* tbl = qs + N_ * DH_;

    const int tid = threadIdx.x;
    const int bh = blockIdx.x;
    const int h = bh % H_;
    const float* kp = g_k + (size_t)bh * N_ * DH_;
    const float* qp = g_q + (size_t)bh * N_ * DH_;

    for (int idx = tid; idx < N_ * DH_; idx += 256) {
        int mm = idx >> 6, d = idx & 63;
        kT[d * KTP + mm] = kp[idx];
        qs[idx] = qp[idx];
    }
    for (int idx = tid; idx < 64 * (KTP - N_); idx += 256) {
        int d = idx / (KTP - N_), mm = N_ + idx % (KTP - N_);
        kT[d * KTP + mm] = 0.f;
    }
    for (int idx = tid; idx < NUM_REL_; idx += 256)
        tbl[idx] = rel_table[idx * H_ + h];
    __syncthreads();

    const int w = tid >> 5, l = tid & 31;
    float* outp = g_attn + (size_t)bh * NN_;

    for (int n0 = w * 4; n0 < N_; n0 += 32) {
        int nr[4];
#pragma unroll
        for (int r = 0; r < 4; r++) nr[r] = min(n0 + r, N_ - 1);
        float acc[4][7];
#pragma unroll
        for (int r = 0; r < 4; r++)
#pragma unroll
            for (int j = 0; j < 7; j++) acc[r][j] = 0.f;

#pragma unroll 4
        for (int d = 0; d < DH_; d++) {
            float qv[4];
#pragma unroll
            for (int r = 0; r < 4; r++) qv[r] = qs[nr[r] * 64 + d];
#pragma unroll
            for (int j = 0; j < 7; j++) {
                float kv = kT[d * KTP + l + 32 * j];
#pragma unroll
                for (int r = 0; r < 4; r++) acc[r][j] = fmaf(qv[r], kv, acc[r][j]);
            }
        }

#pragma unroll
        for (int r = 0; r < 4; r++) {
            int n = n0 + r;
            if (n >= N_) break;
            const int* ridx = rel_index + n * N_;
            float s[7];
#pragma unroll
            for (int j = 0; j < 7; j++) {
                int mm = l + 32 * j;
                s[j] = (mm < N_) ? acc[r][j] + tbl[ridx[mm]] : -1e30f;
            }
            float mx = s[0];
#pragma unroll
            for (int j = 1; j < 7; j++) mx = fmaxf(mx, s[j]);
#pragma unroll
            for (int o = 16; o; o >>= 1) mx = fmaxf(mx, __shfl_xor_sync(0xffffffffu, mx, o));
            float sum = 0.f;
#pragma unroll
            for (int j = 0; j < 7; j++) { float e = __expf(s[j] - mx); s[j] = e; sum += e; }
#pragma unroll
            for (int o = 16; o; o >>= 1) sum += __shfl_xor_sync(0xffffffffu, sum, o);
            float inv = 1.f / sum;
#pragma unroll
            for (int j = 0; j < 7; j++) {
                int mm = l + 32 * j;
                if (mm < N_) outp[(size_t)n * N_ + mm] = s[j] * inv;
            }
        }
    }
}

// =====================================================================
// Kernel: DCF head mix
// =====================================================================
__global__ __launch_bounds__(256) void mix_kernel(const float* __restrict__ coeff)
{
    __shared__ float mixs[12][13];
    const int tid = threadIdx.x;
    if (tid < 144) {
        int k = tid / 12, h = tid % 12;
        mixs[h][k] = coeff[k * 12 + h] + ((h == k) ? 1.f : 0.f);
    }
    __syncthreads();

    const int b = blockIdx.y;
    const int idx = blockIdx.x * 256 + tid;
    if (idx >= NN_) return;
    const float* ap = g_attn + (size_t)b * H_ * NN_ + idx;
    float a[12];
#pragma unroll
    for (int h = 0; h < 12; h++) a[h] = ap[(size_t)h * NN_];
    float* op = g_attn2 + (size_t)b * H_ * NN_ + idx;
#pragma unroll
    for (int k = 0; k < 12; k++) {
        float s = 0.f;
#pragma unroll
        for (int h = 0; h < 12; h++) s = fmaf(a[h], mixs[h][k], s);
        op[(size_t)k * NN_] = s;
    }
}

// =====================================================================
// Kernel: ctx = attn2 @ v
// =====================================================================
__global__ __launch_bounds__(256) void av_gemm()
{
    __shared__ __align__(16) float As[16][68];
    __shared__ __align__(16) float Vs[16][68];
    const int tid = threadIdx.x;
    const int bh = blockIdx.y;
    const int row0 = blockIdx.x * 64;
    const float* A = g_attn2 + (size_t)bh * NN_;
    const float* V = g_v + (size_t)bh * N_ * DH_;
    const int tx = tid & 15, ty = tid >> 4;
    const int vr = tid >> 4;
    const int vc = (tid & 15) << 2;

    float acc[4][4];
#pragma unroll
    for (int i = 0; i < 4; i++)
#pragma unroll
        for (int j = 0; j < 4; j++) acc[i][j] = 0.f;

    for (int k0 = 0; k0 < N_; k0 += 16) {
#pragma unroll
        for (int u = 0; u < 4; u++) {
            int idx = tid + u * 256;
            int r = idx >> 4, kc = idx & 15;
            int n = row0 + r, k = k0 + kc;
            As[kc][r] = (n < N_ && k < N_) ? A[(size_t)n * N_ + k] : 0.f;
        }
        {
            int k = k0 + vr;
            float4 vv = (k < N_) ? *(const float4*)(V + (size_t)k * DH_ + vc)
                                 : make_float4(0.f, 0.f, 0.f, 0.f);
            *(float4*)&Vs[vr][vc] = vv;
        }
        __syncthreads();
#pragma unroll
        for (int kk = 0; kk < 16; kk++) {
            float4 av = *(const float4*)&As[kk][ty << 2];
            float4 bv = *(const float4*)&Vs[kk][tx << 2];
            float aa[4] = {av.x, av.y, av.z, av.w};
            float bb[4] = {bv.x, bv.y, bv.z, bv.w};
#pragma unroll
            for (int i = 0; i < 4; i++)
#pragma unroll
                for (int j = 0; j < 4; j++)
                    acc[i][j] = fmaf(aa[i], bb[j], acc[i][j]);
        }
        __syncthreads();
    }

    const int b = bh / H_, h = bh - b * H_;
#pragma unroll
    for (int i = 0; i < 4; i++) {
        int n = row0 + (ty << 2) + i;
        if (n < N_) {
            float* op = g_ctx + ((size_t)(b * N_ + n)) * C_ + h * DH_ + (tx << 2);
#pragma unroll
            for (int j = 0; j < 4; j++) op[j] = acc[i][j];
        }
    }
}

// =====================================================================
// Host launcher
// =====================================================================
extern "C" void kernel_launch(void* const* d_in, const int* in_sizes, int n_in,
                              void* d_out, int out_size)
{
    const float* x         = (const float*)d_in[0];
    const float* qkv_w     = (const float*)d_in[1];
    const float* q_bias    = (const float*)d_in[2];
    const float* v_bias    = (const float*)d_in[3];
    const float* ss_qkv    = (const float*)d_in[4];
    const float* sh_qkv    = (const float*)d_in[5];
    const float* rel_table = (const float*)d_in[6];
    const float* coeff     = (const float*)d_in[7];
    const float* proj_w    = (const float*)d_in[8];
    const float* proj_b    = (const float*)d_in[9];
    const float* ss_proj   = (const float*)d_in[10];
    const float* sh_proj   = (const float*)d_in[11];
    const int*   rel_index = (const int*)d_in[12];
    float* out = (float*)d_out;

    const int scores_smem = (64 * KTP + N_ * DH_ + NUM_REL_) * 4;
    cudaFuncSetAttribute(scores_kernel, cudaFuncAttributeMaxDynamicSharedMemorySize, scores_smem);
    const int gemm_smem = 4 * SA_;   // 73728 bytes (2 bufs x (A+B))
    cudaFuncSetAttribute(tc_gemm<0>, cudaFuncAttributeMaxDynamicSharedMemorySize, gemm_smem);
    cudaFuncSetAttribute(tc_gemm<1>, cudaFuncAttributeMaxDynamicSharedMemorySize, gemm_smem);

    __nv_bfloat16 *apack, *bqkv, *bproj;
    cudaGetSymbolAddress((void**)&apack, g_apack);
    cudaGetSymbolAddress((void**)&bqkv,  g_bqkv);
    cudaGetSymbolAddress((void**)&bproj, g_bproj);
    float* ctx;
    cudaGetSymbolAddress((void**)&ctx, g_ctx);

    // 1) pack x and qkv weights -> split bf16
    pack_a<<<(M_ * C_ + 255) / 256, 256>>>(x, apack, M_ * C_);
    pack_b<<<(3 * C_ * C_ + 255) / 256, 256>>>(qkv_w, bqkv, 3 * C_ * C_);
    // 2) qkv GEMM (tensor cores via mma.sync) + bias/SSF + scatter
    tc_gemm<0><<<dim3(99, 18), 256, gemm_smem>>>(apack, bqkv, q_bias, v_bias,
                                                 ss_qkv, sh_qkv, nullptr);
    // 3) scores + softmax
    scores_kernel<<<B_ * H_, 256, scores_smem>>>(rel_table, rel_index);
    // 4) head mix
    mix_kernel<<<dim3((NN_ + 255) / 256, B_), 256>>>(coeff);
    // 5) attn @ v
    av_gemm<<<dim3(4, B_ * H_), 256>>>();
    // 6) pack ctx + proj weights, proj GEMM (tensor cores)
    pack_a<<<(M_ * C_ + 255) / 256, 256>>>(ctx, apack, M_ * C_);
    pack_b<<<(C_ * C_ + 255) / 256, 256>>>(proj_w, bproj, C_ * C_);
    tc_gemm<1><<<dim3(99, 6), 256, gemm_smem>>>(apack, bproj, proj_b, nullptr,
                                                ss_proj, sh_proj, out);
}